// round 6
// baseline (speedup 1.0000x reference)
#include <cuda_runtime.h>
#include <cuda_bf16.h>
#include <math.h>
#include <stdint.h>

// Problem constants
#define Vv 50000
#define Ee 256
#define HD 512
#define Hh 256
#define Bb 64
#define Tt 512
#define Kk 16
#define G4H 1024
#define START_IDX 14
#define STOP_IDX 15
#define NEG (-10000.0f)

// ---------------- device scratch ----------------
__device__ __align__(16) float g_Wr2[2 * 1024 * 256];               // [d][col][k], col=j*4+gate
__device__ __align__(16) float g_Gpre[2ull * Tt * Bb * G4H];        // 268 MB
__device__ __align__(16) float g_hs[2ull * Tt * Bb * Hh];           // 67 MB
__device__ float g_feats[(size_t)Tt * Bb * Kk];

// ---------------- f32x2 helpers ----------------
__device__ __forceinline__ void ffma2(unsigned long long& d,
                                      unsigned long long a, unsigned long long b) {
    asm("fma.rn.f32x2 %0, %1, %2, %0;" : "+l"(d) : "l"(a), "l"(b));
}
__device__ __forceinline__ unsigned long long pack2(float x, float y) {
    unsigned long long r;
    asm("mov.b64 %0, {%1, %2};" : "=l"(r) : "f"(x), "f"(y));
    return r;
}
__device__ __forceinline__ float hadd2(unsigned long long v) {
    float lo = __uint_as_float((unsigned)(v & 0xffffffffull));
    float hi = __uint_as_float((unsigned)(v >> 32));
    return lo + hi;
}
__device__ __forceinline__ float fsig(float x) {
    return __fdividef(1.0f, 1.0f + __expf(-x));
}
__device__ __forceinline__ float ftanh(float x) {
    return __fdividef(2.0f, 1.0f + __expf(-2.0f * x)) - 1.0f;
}

// ---------------- cluster mbarrier helpers ----------------
__device__ __forceinline__ uint32_t smem_u32_of(const void* p) {
    uint32_t a;
    asm("{ .reg .u64 t0; cvta.to.shared.u64 t0, %1; cvt.u32.u64 %0, t0; }"
        : "=r"(a) : "l"(p));
    return a;
}
__device__ __forceinline__ void mbar_init(uint32_t mbar, uint32_t cnt) {
    asm volatile("mbarrier.init.shared.b64 [%0], %1;" :: "r"(mbar), "r"(cnt) : "memory");
}
__device__ __forceinline__ void mbar_arrive_expect(uint32_t mbar, uint32_t tx) {
    asm volatile("mbarrier.arrive.expect_tx.shared.b64 _, [%0], %1;"
                 :: "r"(mbar), "r"(tx) : "memory");
}
__device__ __forceinline__ void mbar_wait_cluster(uint32_t mbar, uint32_t parity) {
    asm volatile(
        "{\n\t"
        ".reg .pred P1;\n\t"
        "WAIT_%=:\n\t"
        "mbarrier.try_wait.parity.acquire.cluster.shared::cta.b64 P1, [%0], %1, 0x989680;\n\t"
        "@P1 bra.uni DONE_%=;\n\t"
        "bra.uni WAIT_%=;\n\t"
        "DONE_%=:\n\t"
        "}"
        :: "r"(mbar), "r"(parity) : "memory");
}
__device__ __forceinline__ uint32_t mapa_u32(uint32_t addr, uint32_t rank) {
    uint32_t r;
    asm("mapa.shared::cluster.u32 %0, %1, %2;" : "=r"(r) : "r"(addr), "r"(rank));
    return r;
}
__device__ __forceinline__ void st_async_f64(uint32_t daddr, unsigned long long val,
                                             uint32_t mbar) {
    asm volatile(
        "st.async.weak.shared::cluster.mbarrier::complete_tx::bytes.b64 [%0], %1, [%2];"
        :: "r"(daddr), "l"(val), "r"(mbar) : "memory");
}

// ---------------- kernel 0: reorder recurrent weights ----------------
__global__ void prep_whh_kernel(const float* __restrict__ whh_f,
                                const float* __restrict__ whh_b) {
    int idx = blockIdx.x * blockDim.x + threadIdx.x;   // over 2*1024*256
    int k = idx & 255;
    int col = (idx >> 8) & 1023;
    int d = idx >> 18;
    int gate = col & 3;
    int j = col >> 2;
    const float* w = d ? whh_b : whh_f;
    g_Wr2[idx] = w[(gate * 256 + j) * 256 + k];
}

// ---------------- dummy kernel (rotates the sticky ncu capture slot) --------
__global__ void dummy_kernel() {}

// ---------------- kernel 1: embedding gather + input projection SGEMM ----------------
// Block tile 256m x 64n, BK=8, thread tile 16m x 4n -> ~115 regs, 2 CTAs/SM.
// A natural layout: LDS.128 yields native (m,m+1) pairs for FFMA2.
__global__ __launch_bounds__(256, 2) void input_proj_kernel(
    const int*   __restrict__ sentence,
    const float* __restrict__ emb,
    const float* __restrict__ wih_f, const float* __restrict__ bf,
    const float* __restrict__ wih_b, const float* __restrict__ bbias) {
    const int d = blockIdx.z;
    const float* wih = d ? wih_b : wih_f;
    const float* bias = d ? bbias : bf;

    __shared__ __align__(16) float As[2][8][256];    // 16 KB
    __shared__ __align__(16) float Bs[2][8][64];     // 4 KB

    const int tid = threadIdx.x;
    const int tx = tid & 15;          // n-group (4 cols)
    const int ty = tid >> 4;          // m-group (16 rows)
    const int m0 = blockIdx.y * 256;
    const int c0 = blockIdx.x * 64;

    // A loader: one m-row per thread (8 floats / slab)
    const int mA = m0 + tid;
    const int tok = sentence[(mA & 63) * Tt + (mA >> 6)];
    const float* arow = emb + (size_t)tok * Ee;
    // B loader: row tid>>2, k-offset (tid&3)*2 (2 floats / slab)
    const int cB = c0 + (tid >> 2);
    const int rB = ((cB & 3) << 8) | (cB >> 2);
    const float* brow = wih + (size_t)rB * Ee + (tid & 3) * 2;

    unsigned long long acc2[8][4];
#pragma unroll
    for (int i = 0; i < 8; i++)
#pragma unroll
        for (int j = 0; j < 4; j++) acc2[i][j] = 0ull;

    // prologue: fill buffer 0
    {
        float4 a0 = *(const float4*)(arow + 0);
        float4 a1 = *(const float4*)(arow + 4);
        float2 bv = *(const float2*)(brow);
        float av[8] = {a0.x, a0.y, a0.z, a0.w, a1.x, a1.y, a1.z, a1.w};
#pragma unroll
        for (int i = 0; i < 8; i++) As[0][i][tid] = av[i];
        Bs[0][(tid & 3) * 2 + 0][tid >> 2] = bv.x;
        Bs[0][(tid & 3) * 2 + 1][tid >> 2] = bv.y;
    }
    __syncthreads();

    for (int it = 0; it < 32; it++) {
        const int cur = it & 1;
        float4 a0n, a1n;
        float2 bvn;
        if (it < 31) {
            a0n = *(const float4*)(arow + (it + 1) * 8);
            a1n = *(const float4*)(arow + (it + 1) * 8 + 4);
            bvn = *(const float2*)(brow + (it + 1) * 8);
        }
#pragma unroll
        for (int kk = 0; kk < 8; kk++) {
            const ulonglong2* pa = (const ulonglong2*)&As[cur][kk][ty * 16];
            ulonglong2 p0 = pa[0], p1 = pa[1], p2 = pa[2], p3 = pa[3];
            unsigned long long ra[8] = {p0.x, p0.y, p1.x, p1.y,
                                        p2.x, p2.y, p3.x, p3.y};
            float4 bq = *(const float4*)&Bs[cur][kk][tx * 4];
            unsigned long long rb2[4];
            rb2[0] = pack2(bq.x, bq.x); rb2[1] = pack2(bq.y, bq.y);
            rb2[2] = pack2(bq.z, bq.z); rb2[3] = pack2(bq.w, bq.w);
#pragma unroll
            for (int mp = 0; mp < 8; mp++)
#pragma unroll
                for (int n = 0; n < 4; n++) ffma2(acc2[mp][n], ra[mp], rb2[n]);
        }
        if (it < 31) {
            const int nxt = cur ^ 1;
            float av[8] = {a0n.x, a0n.y, a0n.z, a0n.w, a1n.x, a1n.y, a1n.z, a1n.w};
#pragma unroll
            for (int i = 0; i < 8; i++) As[nxt][i][tid] = av[i];
            Bs[nxt][(tid & 3) * 2 + 0][tid >> 2] = bvn.x;
            Bs[nxt][(tid & 3) * 2 + 1][tid >> 2] = bvn.y;
        }
        __syncthreads();
    }

    float bsv[4];
#pragma unroll
    for (int n = 0; n < 4; n++) {
        int c = c0 + tx * 4 + n;
        bsv[n] = bias[((c & 3) << 8) | (c >> 2)];
    }
#pragma unroll
    for (int mp = 0; mp < 8; mp++) {
        const int me = m0 + ty * 16 + 2 * mp;      // even m
        float oe[4], oo[4];
#pragma unroll
        for (int n = 0; n < 4; n++) {
            unsigned long long v = acc2[mp][n];
            oe[n] = __uint_as_float((unsigned)(v & 0xffffffffull)) + bsv[n];
            oo[n] = __uint_as_float((unsigned)(v >> 32)) + bsv[n];
        }
        {
            int t = me >> 6, b = me & 63;
            float* outp = g_Gpre + (((size_t)d * Tt + t) * Bb + b) * G4H + c0 + tx * 4;
            *(float4*)(outp) = make_float4(oe[0], oe[1], oe[2], oe[3]);
        }
        {
            int mo = me + 1;
            int t = mo >> 6, b = mo & 63;
            float* outp = g_Gpre + (((size_t)d * Tt + t) * Bb + b) * G4H + c0 + tx * 4;
            *(float4*)(outp) = make_float4(oo[0], oo[1], oo[2], oo[3]);
        }
    }
}

// ---------------- kernel 2: LSTM recurrence ----------------
// 128 CTAs, cluster 8. cid=blk>>3: d=cid>>3, batch group bg=cid&7.
// GEMM phase: warp w <-> k-chunk w (= source CTA w's h range), lane = local j.
// Per (buffer, source) mbarrier (16 total, expect 1 KB each) -> warp w waits
// ONLY on its own source => DSMEM flight overlaps other warps' GEMM.
// Cross-warp reduce via part_sm (swizzled, 4-wavefront optimal).
// Cell phase: thread t -> (j_own = t>>3, b_own = t&7).
__global__ void __cluster_dims__(8, 1, 1) __launch_bounds__(256, 1) lstm_rec_kernel() {
    const int tidx = threadIdx.x;
    const int w = tidx >> 5;           // k-chunk / source rank
    const int lane = tidx & 31;        // local j in GEMM phase
    const int j_own = tidx >> 3;       // local j in cell phase
    const int b_own = tidx & 7;        // local batch in cell phase
    const int cid = blockIdx.x >> 3;
    const int r = blockIdx.x & 7;
    const int d = cid >> 3;
    const int bg = cid & 7;
    const int bat = bg * 8 + b_own;
    const int jcell = r * 32 + j_own;
    const int jg = r * 32 + lane;

    __shared__ __align__(16) float h_sm[2][8][256];      // 16 KB
    __shared__ __align__(16) float4 part_sm[2048];       // 32 KB
    __shared__ __align__(8) unsigned long long mbars[16];

    // ---- weights into registers: col = jg*4+g, k in [w*32, w*32+32) ----
    unsigned long long wu[4][16];
    const float* wbase = g_Wr2 + (size_t)d * 1024 * 256;
#pragma unroll
    for (int g = 0; g < 4; g++) {
        const ulonglong2* p = (const ulonglong2*)(wbase + (size_t)(jg * 4 + g) * 256 + w * 32);
#pragma unroll
        for (int q = 0; q < 8; q++) {
            ulonglong2 v = p[q];
            wu[g][2 * q + 0] = v.x;
            wu[g][2 * q + 1] = v.y;
        }
    }

    // zero step-0 h buffer
    for (int i = tidx; i < 8 * 256; i += 256) ((float*)h_sm[0])[i] = 0.0f;
    float c = 0.0f;

    const uint32_t h_base = smem_u32_of(h_sm);
    const uint32_t mb_base = smem_u32_of(mbars);
    const uint32_t dmb = mb_base - h_base;

    if (tidx < 16) {
        mbar_init(mb_base + tidx * 8, 1);
        mbar_arrive_expect(mb_base + tidx * 8, 1024);   // pre-arm both buffers
    }
    __syncthreads();
    asm volatile("barrier.cluster.arrive.aligned;" ::: "memory");
    asm volatile("barrier.cluster.wait.aligned;" ::: "memory");

    uint32_t ph[8];
#pragma unroll
    for (int rk = 0; rk < 8; rk++) ph[rk] = mapa_u32(h_base, rk);

    const uint32_t hoffA = (uint32_t)((b_own * 256 + jcell) * 4);
    const bool sender = ((tidx & 8) == 0);
    const int w32 = w * 32;

    const int t0 = d ? (Tt - 1) : 0;
    const int tstep = d ? -1 : 1;
    const float4* gpre4 = (const float4*)g_Gpre;

    float4 g4 = gpre4[(((size_t)d * Tt + t0) * Bb + bat) * 256 + jcell];

    for (int s = 0; s < Tt; s++) {
        const int t = t0 + s * tstep;
        const int cur = s & 1;

        if (s > 0) {
            uint32_t mb = mb_base + (uint32_t)((cur * 8 + w) * 8);
            mbar_wait_cluster(mb, ((s - 1) >> 1) & 1);
            if (lane == 0) mbar_arrive_expect(mb, 1024);   // re-arm for step s+2
        }

        // ---- GEMM: partials for (j = lane, gates, all 8 batches, k-chunk w) ----
        float prt[4][8];
#pragma unroll
        for (int b = 0; b < 8; b++) {
            unsigned long long a2[4] = {0ull, 0ull, 0ull, 0ull};
            const ulonglong2* hp = (const ulonglong2*)&h_sm[cur][b][w32];
#pragma unroll
            for (int i = 0; i < 8; i++) {
                ulonglong2 h4 = hp[i];
                ffma2(a2[0], wu[0][2 * i], h4.x); ffma2(a2[0], wu[0][2 * i + 1], h4.y);
                ffma2(a2[1], wu[1][2 * i], h4.x); ffma2(a2[1], wu[1][2 * i + 1], h4.y);
                ffma2(a2[2], wu[2][2 * i], h4.x); ffma2(a2[2], wu[2][2 * i + 1], h4.y);
                ffma2(a2[3], wu[3][2 * i], h4.x); ffma2(a2[3], wu[3][2 * i + 1], h4.y);
            }
#pragma unroll
            for (int g = 0; g < 4; g++) prt[g][b] = hadd2(a2[g]);
        }

        // ---- scatter partials to smem (residue-balanced swizzle) ----
#pragma unroll
        for (int b = 0; b < 8; b++) {
            uint32_t u = (uint32_t)(w * 256 + b * 32 + ((lane & 24) | ((lane + b) & 7)));
            part_sm[u] = make_float4(prt[0][b], prt[1][b], prt[2][b], prt[3][b]);
        }
        __syncthreads();

        // prefetch next step's Gpre
        float4 g4n = g4;
        if (s + 1 < Tt)
            g4n = gpre4[(((size_t)d * Tt + (t + tstep)) * Bb + bat) * 256 + jcell];

        // ---- gather: sum over 8 k-chunks for (j_own, b_own) ----
        float s0 = 0.0f, s1 = 0.0f, s2 = 0.0f, s3 = 0.0f;
#pragma unroll
        for (int w2 = 0; w2 < 8; w2++) {
            uint32_t u = (uint32_t)(w2 * 256 + b_own * 32 +
                                    ((j_own & 24) | ((j_own + b_own) & 7)));
            float4 v = part_sm[u];
            s0 += v.x; s1 += v.y; s2 += v.z; s3 += v.w;
        }
        __syncthreads();   // protect part_sm against next step's scatter

        // ---- LSTM cell for (jcell, bat) ----
        float a0 = s0 + g4.x;
        float a1 = s1 + g4.y;
        float a2v = s2 + g4.z;
        float a3 = s3 + g4.w;
        float ig = fsig(a0), fg = fsig(a1), gv = ftanh(a2v), og = fsig(a3);
        c = fg * c + ig * gv;
        float h = og * ftanh(c);

        g_hs[(((size_t)d * Tt + t) * Bb + bat) * Hh + jcell] = h;

        // pair with j-neighbor (tid^8) and broadcast b64 to all ranks
        float hN = __shfl_xor_sync(0xffffffffu, h, 8);
        if (s + 1 < Tt && sender) {
            unsigned long long hv = pack2(h, hN);
            const uint32_t nxt = cur ^ 1;
            const uint32_t doff = nxt * 8192u + hoffA;
            const uint32_t moff = dmb + (uint32_t)((nxt * 8 + r) * 8);
#pragma unroll
            for (int rk = 0; rk < 8; rk++)
                st_async_f64(ph[rk] + doff, hv, ph[rk] + moff);
        }
        g4 = g4n;
    }
}

// ---------------- kernel 3: emission features (w_out staged in smem) ---------
__global__ __launch_bounds__(256) void feats_kernel(const float* __restrict__ w_out,
                                                    const float* __restrict__ b_out) {
    const int lane = threadIdx.x & 31;
    const int warp = threadIdx.x >> 5;
    const int m = blockIdx.x * 8 + warp;
    const int t = m >> 6, b = m & 63;

    __shared__ __align__(16) float w_sm[Kk * HD];    // 32 KB
    __shared__ float f_sm[8][16];

    for (int i = threadIdx.x; i < (Kk * HD) / 4; i += 256)
        ((float4*)w_sm)[i] = ((const float4*)w_out)[i];
    __syncthreads();

    float acc[16];
#pragma unroll
    for (int kk = 0; kk < 16; kk++) acc[kk] = 0.0f;

    const float* hf = g_hs + ((size_t)t * Bb + b) * Hh;
    const float* hb = g_hs + ((size_t)Tt * Bb * Hh) + ((size_t)t * Bb + b) * Hh;

#pragma unroll
    for (int i = 0; i < 16; i++) {
        int dd = i * 32 + lane;
        float hv = (dd < Hh) ? hf[dd] : hb[dd - Hh];
#pragma unroll
        for (int kk = 0; kk < 16; kk++) acc[kk] += hv * w_sm[kk * HD + dd];
    }
#pragma unroll
    for (int kk = 0; kk < 16; kk++) {
        float s = acc[kk];
        s += __shfl_down_sync(0xffffffffu, s, 16);
        s += __shfl_down_sync(0xffffffffu, s, 8);
        s += __shfl_down_sync(0xffffffffu, s, 4);
        s += __shfl_down_sync(0xffffffffu, s, 2);
        s += __shfl_down_sync(0xffffffffu, s, 1);
        if (lane == 0) f_sm[warp][kk] = s;
    }
    __syncwarp();
    if (lane < 16)
        g_feats[((size_t)t * Bb + b) * Kk + lane] = f_sm[warp][lane] + b_out[lane];
}

// ---------------- kernel 4: Viterbi forward + backtrace ----------------
__global__ __launch_bounds__(32) void viterbi_kernel(const float* __restrict__ trans,
                                                     float* __restrict__ out) {
    const int b = blockIdx.x;
    const int lane = threadIdx.x;

    __shared__ unsigned char bp_sm[Tt][16];

    float trans_r[16];
#pragma unroll
    for (int p = 0; p < 16; p++)
        trans_r[p] = (lane < 16) ? trans[lane * 16 + p] : 0.0f;

    float fv = (lane == START_IDX) ? 0.0f : NEG;
    if (lane >= 16) fv = NEG;

    float feat_n = (lane < 16) ? g_feats[((size_t)0 * Bb + b) * Kk + lane] : 0.0f;

    for (int t = 0; t < Tt; t++) {
        float feat = feat_n;
        if (t + 1 < Tt)
            feat_n = (lane < 16) ? g_feats[((size_t)(t + 1) * Bb + b) * Kk + lane] : 0.0f;
        float m = -3.4e38f;
        int am = 0;
#pragma unroll
        for (int p = 0; p < 16; p++) {
            float v = __shfl_sync(0xffffffffu, fv, p) + trans_r[p];
            if (v > m) { m = v; am = p; }
        }
        float nfv = m + feat;
        fv = (lane < 16) ? nfv : NEG;
        if (lane < 16) bp_sm[t][lane] = (unsigned char)am;
    }
    __syncwarp();

    float best = -3.4e38f;
    int bt = 0;
#pragma unroll
    for (int s = 0; s < 16; s++) {
        float v = __shfl_sync(0xffffffffu, fv, s);
        float tv = v + trans[STOP_IDX * 16 + s];
        if (tv > best) { best = tv; bt = s; }
    }
    if (lane == 0) {
        out[b] = best;
        int tag = bt;
        for (int t = Tt - 1; t >= 0; t--) {
            out[64 + (size_t)t * Bb + b] = (float)tag;
            tag = bp_sm[t][tag];
        }
    }
}

// ---------------- launcher ----------------
extern "C" void kernel_launch(void* const* d_in, const int* in_sizes, int n_in,
                              void* d_out, int out_size) {
    const int*   sentence = (const int*)d_in[0];
    const float* emb      = (const float*)d_in[1];
    const float* w_ih_f   = (const float*)d_in[2];
    const float* w_hh_f   = (const float*)d_in[3];
    const float* b_f      = (const float*)d_in[4];
    const float* w_ih_b   = (const float*)d_in[5];
    const float* w_hh_b   = (const float*)d_in[6];
    const float* b_b      = (const float*)d_in[7];
    const float* w_out    = (const float*)d_in[8];
    const float* b_out    = (const float*)d_in[9];
    const float* trans    = (const float*)d_in[10];
    float* out = (float*)d_out;
    (void)in_sizes; (void)n_in; (void)out_size;

    prep_whh_kernel<<<2048, 256>>>(w_hh_f, w_hh_b);
    dim3 pg(G4H / 64, (Tt * Bb) / 256, 2);
    input_proj_kernel<<<pg, 256>>>(sentence, emb, w_ih_f, b_f, w_ih_b, b_b);
    dummy_kernel<<<1, 1>>>();   // rotates ncu's sticky capture slot onto lstm
    lstm_rec_kernel<<<128, 256>>>();
    feats_kernel<<<(Tt * Bb) / 8, 256>>>(w_out, b_out);
    viterbi_kernel<<<Bb, 32>>>(trans, out);
}